// round 3
// baseline (speedup 1.0000x reference)
#include <cuda_runtime.h>

#define BATCH 4
#define CIN   64
#define HH    128
#define WW    128
#define COUT  64
#define KDIM  576   // CIN * 9

// Scratch (static device globals — no runtime allocation)
__device__ float g_x_nhwc[BATCH * HH * WW * CIN];   // 16.8 MB
__device__ float g_off[BATCH * HH * WW * 18];       // 4.7 MB

#define BAR_SYNC(id, cnt)   asm volatile("bar.sync %0, %1;"   :: "r"(id), "r"(cnt) : "memory")
#define BAR_ARRIVE(id, cnt) asm volatile("bar.arrive %0, %1;" :: "r"(id), "r"(cnt) : "memory")

// ---------------------------------------------------------------------------
// K0: NCHW -> NHWC transpose of x
// ---------------------------------------------------------------------------
__global__ void k_transpose(const float* __restrict__ x) {
    __shared__ float t[32][33];
    int b = blockIdx.z >> 7;
    int h = blockIdx.z & 127;
    int w0 = blockIdx.x * 32;
    int c0 = blockIdx.y * 32;
    int tx = threadIdx.x, ty = threadIdx.y;
#pragma unroll
    for (int r = 0; r < 32; r += 8)
        t[ty + r][tx] = x[(((b * CIN) + (c0 + ty + r)) * HH + h) * WW + w0 + tx];
    __syncthreads();
#pragma unroll
    for (int r = 0; r < 32; r += 8)
        g_x_nhwc[(((b * HH) + h) * WW + (w0 + ty + r)) * CIN + c0 + tx] = t[tx][ty + r];
}

// ---------------------------------------------------------------------------
// K1: offset conv (18ch 3x3 conv + bias), f32x2 inner, output reordered
// ---------------------------------------------------------------------------
#define K1_WS_STRIDE 24
#define K1_SMEM_BYTES ((64 * 324 + 576 * K1_WS_STRIDE) * 4)

__global__ void k_offsets(const float* __restrict__ x,
                          const float* __restrict__ Woff,
                          const float* __restrict__ boff) {
    extern __shared__ float sm1[];
    float* xs = sm1;              // [c][li][lj] : 64*18*18
    float* ws = sm1 + 64 * 324;   // [k][o pad24]

    int b  = blockIdx.z;
    int i0 = blockIdx.y * 16;
    int j0 = blockIdx.x * 16;
    int tid = threadIdx.x;

    for (int e = tid; e < 64 * 324; e += 256) {
        int c = e / 324;
        int rem = e - c * 324;
        int li = rem / 18, lj = rem - li * 18;
        int gi = i0 + li - 1, gj = j0 + lj - 1;
        float v = 0.f;
        if ((unsigned)gi < 128u && (unsigned)gj < 128u)
            v = x[((b * 64 + c) * 128 + gi) * 128 + gj];
        xs[e] = v;
    }
    for (int e = tid; e < 18 * 576; e += 256) {
        int o = e / 576;
        int k = e - o * 576;
        ws[k * K1_WS_STRIDE + o] = Woff[e];
    }
    __syncthreads();

    int ty = tid >> 4, tx = tid & 15;
    unsigned long long acc[9];
#pragma unroll
    for (int q = 0; q < 9; q++) {
        float blo = __ldg(&boff[2 * q]);
        float bhi = __ldg(&boff[2 * q + 1]);
        asm("mov.b64 %0, {%1, %2};" : "=l"(acc[q]) : "f"(blo), "f"(bhi));
    }

    for (int c = 0; c < 64; c++) {
        float xv[9];
#pragma unroll
        for (int t = 0; t < 9; t++)
            xv[t] = xs[c * 324 + (ty + t / 3) * 18 + (tx + t % 3)];
#pragma unroll
        for (int t = 0; t < 9; t++) {
            unsigned long long ss;
            asm("mov.b64 %0, {%1, %1};" : "=l"(ss) : "f"(xv[t]));
            const float* wp = ws + (c * 9 + t) * K1_WS_STRIDE;
            ulonglong2 wA = *(const ulonglong2*)(wp);
            ulonglong2 wB = *(const ulonglong2*)(wp + 4);
            ulonglong2 wC = *(const ulonglong2*)(wp + 8);
            ulonglong2 wD = *(const ulonglong2*)(wp + 12);
            unsigned long long wE = *(const unsigned long long*)(wp + 16);
            asm("fma.rn.f32x2 %0, %1, %2, %0;" : "+l"(acc[0]) : "l"(ss), "l"(wA.x));
            asm("fma.rn.f32x2 %0, %1, %2, %0;" : "+l"(acc[1]) : "l"(ss), "l"(wA.y));
            asm("fma.rn.f32x2 %0, %1, %2, %0;" : "+l"(acc[2]) : "l"(ss), "l"(wB.x));
            asm("fma.rn.f32x2 %0, %1, %2, %0;" : "+l"(acc[3]) : "l"(ss), "l"(wB.y));
            asm("fma.rn.f32x2 %0, %1, %2, %0;" : "+l"(acc[4]) : "l"(ss), "l"(wC.x));
            asm("fma.rn.f32x2 %0, %1, %2, %0;" : "+l"(acc[5]) : "l"(ss), "l"(wC.y));
            asm("fma.rn.f32x2 %0, %1, %2, %0;" : "+l"(acc[6]) : "l"(ss), "l"(wD.x));
            asm("fma.rn.f32x2 %0, %1, %2, %0;" : "+l"(acc[7]) : "l"(ss), "l"(wD.y));
            asm("fma.rn.f32x2 %0, %1, %2, %0;" : "+l"(acc[8]) : "l"(ss), "l"(wE));
        }
    }
    // acc[n] = (row_off_n, col_off_n) after the even/odd interleave reorder
    float* op = g_off + (((b * 128) + i0 + ty) * 128 + (j0 + tx)) * 18;
#pragma unroll
    for (int n = 0; n < 9; n++) {
        float lo, hi;
        asm("mov.b64 {%0, %1}, %2;" : "=f"(lo), "=f"(hi) : "l"(acc[n]));
        op[n]     = lo;
        op[9 + n] = hi;
    }
}

// ---------------------------------------------------------------------------
// K2: persistent, warp-specialized. 16-px tiles, double-buffered S + taps.
// Warps 0-3: GEMM (f32x2) + store. Warps 4-7: taps + sampling.
// ---------------------------------------------------------------------------
#define SM2_WS (576 * 64)           // 36864 fl
#define SM2_S  (16 * 577)           //  9232 fl per buffer
#define SM2_T  (144 * 4)            //   576 per buffer (each of tw / tixs)
#define K2_SMEM_BYTES ((SM2_WS + 2 * SM2_S + 4 * SM2_T) * 4)   // 230528 B

#define BID_FULL0  1
#define BID_EMPTY0 3
#define BID_SAMP   5

__global__ void __launch_bounds__(256, 1) k_main(const float* __restrict__ Wc,
                                                 float* __restrict__ out) {
    extern __shared__ float sm2[];
    float* Ws  = sm2;                       // [576][64]
    float* Sb[2];
    Sb[0] = Ws + SM2_WS;
    Sb[1] = Sb[0] + SM2_S;
    float* twb[2];
    twb[0] = Sb[1] + SM2_S;
    twb[1] = twb[0] + SM2_T;
    int* tib[2];
    tib[0] = (int*)(twb[1] + SM2_T);
    tib[1] = tib[0] + SM2_T;

    int tid = threadIdx.x;

    // Stage W once: Ws[k][co] = W_conv[co][k]
    for (int e = tid; e < COUT * KDIM; e += 256) {
        int co = e / 576;
        int k  = e - co * 576;
        Ws[k * 64 + co] = Wc[e];
    }
    __syncthreads();

    const int NT = 4096;  // 16-px tiles

    if (tid < 128) {
        // ================= GEMM role (warps 0-3) =================
        int px = tid & 15;
        int cg = tid >> 4;          // 0..7 -> co base cg*8
        int buf = 0;
        for (int tile = blockIdx.x; tile < NT; tile += gridDim.x) {
            int b   = tile >> 10;
            int rem = tile & 1023;
            int i   = rem >> 3;
            int j0  = (rem & 7) << 4;

            BAR_SYNC(BID_FULL0 + buf, 256);

            const float* Srow  = Sb[buf] + px * 577;
            const float* Wbase = Ws + cg * 8;
            unsigned long long a01 = 0ull, a23 = 0ull, a45 = 0ull, a67 = 0ull;
#pragma unroll 8
            for (int k = 0; k < 576; k++) {
                float s = Srow[k];
                unsigned long long ss;
                asm("mov.b64 %0, {%1, %1};" : "=l"(ss) : "f"(s));
                const float* wp = Wbase + k * 64;
                ulonglong2 w0 = *(const ulonglong2*)(wp);
                ulonglong2 w1 = *(const ulonglong2*)(wp + 4);
                asm("fma.rn.f32x2 %0, %1, %2, %0;" : "+l"(a01) : "l"(ss), "l"(w0.x));
                asm("fma.rn.f32x2 %0, %1, %2, %0;" : "+l"(a23) : "l"(ss), "l"(w0.y));
                asm("fma.rn.f32x2 %0, %1, %2, %0;" : "+l"(a45) : "l"(ss), "l"(w1.x));
                asm("fma.rn.f32x2 %0, %1, %2, %0;" : "+l"(a67) : "l"(ss), "l"(w1.y));
            }
            BAR_ARRIVE(BID_EMPTY0 + buf, 256);   // release sampler ASAP

            float o[8];
            asm("mov.b64 {%0, %1}, %2;" : "=f"(o[0]), "=f"(o[1]) : "l"(a01));
            asm("mov.b64 {%0, %1}, %2;" : "=f"(o[2]), "=f"(o[3]) : "l"(a23));
            asm("mov.b64 {%0, %1}, %2;" : "=f"(o[4]), "=f"(o[5]) : "l"(a45));
            asm("mov.b64 {%0, %1}, %2;" : "=f"(o[6]), "=f"(o[7]) : "l"(a67));

            float* op = out + (((b * 64 + cg * 8) * 128 + i) * 128) + j0 + px;
#pragma unroll
            for (int u = 0; u < 8; u++)
                op[u * 16384] = o[u];

            buf ^= 1;
        }
    } else {
        // ================= Sampler role (warps 4-7) =================
        int ts = tid - 128;
        int buf = 0, n = 0;
        for (int tile = blockIdx.x; tile < NT; tile += gridDim.x, n++) {
            int b   = tile >> 10;
            int rem = tile & 1023;
            int i   = rem >> 3;
            int j0  = (rem & 7) << 4;

            if (n >= 2) BAR_SYNC(BID_EMPTY0 + buf, 256);

            float* tw   = twb[buf];
            int*   tixs = tib[buf];

            // --- taps: 144 (px, n9) pairs over 128 threads ---
            for (int pn = ts; pn < 144; pn += 128) {
                int px = pn / 9;
                int nn = pn - px * 9;
                const float* ofp = g_off + (((b * 128) + i) * 128 + (j0 + px)) * 18;
                float pr = (float)(i + nn / 3) + ofp[nn];
                float pc = (float)(j0 + px + nn % 3) + ofp[9 + nn];

                float flr = floorf(pr);
                int   rl  = min(max((int)flr, 0), 129);
                int   rr  = min(max((int)flr + 1, 0), 129);
                float pm  = ((pr < 1.f) || (pr > 128.f)) ? flr : pr;
                pm = fminf(fmaxf(pm, 0.f), 129.f);
                float wrl = 1.f + ((float)rl - pm);
                float wrr = 1.f - ((float)rr - pm);

                float flc = floorf(pc);
                int   cl  = min(max((int)flc, 0), 129);
                int   cr  = min(max((int)flc + 1, 0), 129);
                float qm  = ((pc < 1.f) || (pc > 128.f)) ? flc : pc;
                qm = fminf(fmaxf(qm, 0.f), 129.f);
                float wcl = 1.f + ((float)cl - qm);
                float wcr = 1.f - ((float)cr - qm);

                int   rs[2]  = {rl, rr};
                float wr2[2] = {wrl, wrr};
                int   cs[2]  = {cl, cr};
                float wc2[2] = {wcl, wcr};
#pragma unroll
                for (int t = 0; t < 4; t++) {
                    int R  = rs[t >> 1];
                    int Cq = cs[t & 1];
                    float w = wr2[t >> 1] * wc2[t & 1];
                    bool ok = (R >= 1) && (R <= 128) && (Cq >= 1) && (Cq <= 128);
                    tixs[pn * 4 + t] = ok ? ((R - 1) * 128 + (Cq - 1)) * 64 : 0;
                    tw[pn * 4 + t]   = ok ? w : 0.f;
                }
            }
            BAR_SYNC(BID_SAMP, 128);   // taps visible to all sampler warps

            // --- sampling: 2304 tasks = 144 (px,n9) x 16 ch-groups ---
            float* S = Sb[buf];
            const float* xb = g_x_nhwc + b * (128 * 128 * 64);
#pragma unroll 6
            for (int it = 0; it < 18; it++) {
                int tt  = it * 128 + ts;
                int pn  = tt >> 4;
                int cig = tt & 15;
                int px  = pn / 9;
                int nn  = pn - px * 9;
                float ax = 0.f, ay = 0.f, az = 0.f, aw = 0.f;
#pragma unroll
                for (int t = 0; t < 4; t++) {
                    float w = tw[pn * 4 + t];
                    const float4 v = *(const float4*)(xb + tixs[pn * 4 + t] + cig * 4);
                    ax += w * v.x; ay += w * v.y; az += w * v.z; aw += w * v.w;
                }
                float* sp = S + px * 577 + (cig * 4) * 9 + nn;
                sp[0] = ax; sp[9] = ay; sp[18] = az; sp[27] = aw;
            }
            BAR_ARRIVE(BID_FULL0 + buf, 256);
            buf ^= 1;
        }
    }
}

// ---------------------------------------------------------------------------
extern "C" void kernel_launch(void* const* d_in, const int* in_sizes, int n_in,
                              void* d_out, int out_size) {
    const float* x    = (const float*)d_in[0];
    const float* Woff = (const float*)d_in[1];
    const float* boff = (const float*)d_in[2];
    const float* Wc   = (const float*)d_in[3];
    float* out = (float*)d_out;

    cudaFuncSetAttribute(k_offsets, cudaFuncAttributeMaxDynamicSharedMemorySize, K1_SMEM_BYTES);
    cudaFuncSetAttribute(k_main,    cudaFuncAttributeMaxDynamicSharedMemorySize, K2_SMEM_BYTES);

    dim3 tb0(32, 8);
    dim3 tg0(WW / 32, CIN / 32, BATCH * HH);
    k_transpose<<<tg0, tb0>>>(x);

    dim3 tg1(WW / 16, HH / 16, BATCH);
    k_offsets<<<tg1, 256, K1_SMEM_BYTES>>>(x, Woff, boff);

    k_main<<<148, 256, K2_SMEM_BYTES>>>(Wc, out);
}

// round 7
// speedup vs baseline: 1.7612x; 1.7612x over previous
#include <cuda_runtime.h>
#include <cuda_fp16.h>
#include <cstdint>

#define BATCH 4
#define CIN   64
#define COUT  64
#define HH    128
#define WW    128

// Scratch (static device globals — no runtime allocation)
__device__ float g_x_nhwc[BATCH * HH * WW * CIN];           // 16.8 MB
__device__ float g_off[BATCH * HH * WW * 18];               // 4.7 MB
__device__ __align__(16) unsigned char g_wf16[73728];       // W fp16, swizzled

#define SMEM_BYTES 230528

// k_mma (tcgen05 path) smem layout
#define SW_OFF     147456                   // A: [n(9)][16 atoms][1024B]
#define SW_BYTES   73728                    // W: [n(9)][8 atoms][1024B]
#define TAPW_OFF   (SW_OFF + SW_BYTES)      // float[128][4]
#define TAPI_OFF   (TAPW_OFF + 2048)        // int[128][4]
#define CTRL_OFF   (TAPI_OFF + 2048)        // tmem ptr @0, mbar @8

#define K1_WS_STRIDE 24
#define K1_SMEM_BYTES ((64 * 324 + 576 * K1_WS_STRIDE) * 4)

// idesc kind::f16: dtype=F32(1<<4), atype/btype=F16(0), N=64 (8<<17), M=128 (8<<24)
#define IDESC_F16 0x8100010u

// ---------------------------------------------------------------------------
// helpers
// ---------------------------------------------------------------------------
__device__ __forceinline__ uint32_t smem_u32(const void* p) {
    uint32_t a;
    asm("{ .reg .u64 t; cvta.to.shared.u64 t, %1; cvt.u32.u64 %0, t; }" : "=r"(a) : "l"(p));
    return a;
}

__device__ __forceinline__ void compute_taps(float pr, float pc, int* ti, float* tw) {
    float flr = floorf(pr);
    int   rl  = min(max((int)flr, 0), 129);
    int   rr  = min(max((int)flr + 1, 0), 129);
    float pm  = ((pr < 1.f) || (pr > 128.f)) ? flr : pr;
    pm = fminf(fmaxf(pm, 0.f), 129.f);
    float wrl = 1.f + ((float)rl - pm);
    float wrr = 1.f - ((float)rr - pm);

    float flc = floorf(pc);
    int   cl  = min(max((int)flc, 0), 129);
    int   cr  = min(max((int)flc + 1, 0), 129);
    float qm  = ((pc < 1.f) || (pc > 128.f)) ? flc : pc;
    qm = fminf(fmaxf(qm, 0.f), 129.f);
    float wcl = 1.f + ((float)cl - qm);
    float wcr = 1.f - ((float)cr - qm);

    int   rs[2]  = {rl, rr};
    float wr2[2] = {wrl, wrr};
    int   cs[2]  = {cl, cr};
    float wc2[2] = {wcl, wcr};
#pragma unroll
    for (int t = 0; t < 4; t++) {
        int R  = rs[t >> 1];
        int Cq = cs[t & 1];
        float w = wr2[t >> 1] * wc2[t & 1];
        bool ok = (R >= 1) && (R <= 128) && (Cq >= 1) && (Cq <= 128);
        ti[t] = ok ? ((R - 1) * 128 + (Cq - 1)) * 64 : 0;
        tw[t] = ok ? w : 0.f;
    }
}

#if defined(__CUDA_ARCH_FEAT_SM103_ALL)
__device__ __forceinline__ bool elect1() {
    uint32_t p;
    asm volatile("{ .reg .pred p; elect.sync _|p, 0xFFFFFFFF; selp.b32 %0, 1, 0, p; }" : "=r"(p));
    return p != 0;
}
__device__ __forceinline__ void mma_f16_ss(uint32_t d, uint64_t ad, uint64_t bd,
                                           uint32_t idesc, bool acc) {
    uint32_t en = acc ? 1u : 0u, z = 0u;
    asm volatile(
        "{\n\t.reg .pred p;\n\tsetp.ne.u32 p, %5, 0;\n\t"
        "tcgen05.mma.cta_group::1.kind::f16 [%0], %1, %2, %3, {%4, %4, %4, %4}, p;\n\t}"
        :: "r"(d), "l"(ad), "l"(bd), "r"(idesc), "r"(z), "r"(en) : "memory");
}
__device__ __forceinline__ void mbar_wait(uint32_t mbar, int phase) {
    uint32_t done;
    asm volatile(
        "{\n\t.reg .pred p;\n\t"
        "mbarrier.try_wait.parity.acquire.cta.shared::cta.b64 p, [%1], %2;\n\t"
        "selp.b32 %0, 1, 0, p;\n\t}"
        : "=r"(done) : "r"(mbar), "r"((uint32_t)phase) : "memory");
    if (!done) {
        asm volatile(
            "{\n\t.reg .pred P1;\n\t"
            "W_%=:\n\t"
            "mbarrier.try_wait.parity.acquire.cta.shared::cta.b64 P1, [%0], %1, 0x989680;\n\t"
            "@P1 bra D_%=;\n\t"
            "bra W_%=;\n\t"
            "D_%=:\n\t}"
            :: "r"(mbar), "r"((uint32_t)phase) : "memory");
    }
}
__device__ __forceinline__ void ldtm32(uint32_t* r, uint32_t addr) {
    asm volatile(
        "tcgen05.ld.sync.aligned.32x32b.x32.b32 "
        "{%0, %1, %2, %3, %4, %5, %6, %7, %8, %9, %10, %11, %12, %13, %14, %15, "
        " %16, %17, %18, %19, %20, %21, %22, %23, %24, %25, %26, %27, %28, %29, %30, %31}, [%32];"
        : "=r"(r[0]), "=r"(r[1]), "=r"(r[2]), "=r"(r[3]), "=r"(r[4]), "=r"(r[5]), "=r"(r[6]), "=r"(r[7]),
          "=r"(r[8]), "=r"(r[9]), "=r"(r[10]), "=r"(r[11]), "=r"(r[12]), "=r"(r[13]), "=r"(r[14]), "=r"(r[15]),
          "=r"(r[16]), "=r"(r[17]), "=r"(r[18]), "=r"(r[19]), "=r"(r[20]), "=r"(r[21]), "=r"(r[22]), "=r"(r[23]),
          "=r"(r[24]), "=r"(r[25]), "=r"(r[26]), "=r"(r[27]), "=r"(r[28]), "=r"(r[29]), "=r"(r[30]), "=r"(r[31])
        : "r"(addr));
}
// SMEM descriptor: SW128, version=1 (Blackwell), SBO=64, LBO=1
__device__ __forceinline__ uint64_t make_desc(uint32_t base) {
    const uint64_t BASE =
        (uint64_t(2) << 61) | (uint64_t(1) << 46) | (uint64_t(64) << 32) | (uint64_t(1) << 16);
    return BASE | ((uint64_t)(base >> 4) & 0x3FFF);
}
#endif

// ---------------------------------------------------------------------------
// K0: NCHW -> NHWC transpose (proven)
// ---------------------------------------------------------------------------
__global__ void k_transpose(const float* __restrict__ x) {
    __shared__ float t[32][33];
    int b = blockIdx.z >> 7;
    int h = blockIdx.z & 127;
    int w0 = blockIdx.x * 32;
    int c0 = blockIdx.y * 32;
    int tx = threadIdx.x, ty = threadIdx.y;
#pragma unroll
    for (int r = 0; r < 32; r += 8)
        t[ty + r][tx] = x[(((b * CIN) + (c0 + ty + r)) * HH + h) * WW + w0 + tx];
    __syncthreads();
#pragma unroll
    for (int r = 0; r < 32; r += 8)
        g_x_nhwc[(((b * HH) + h) * WW + (w0 + ty + r)) * CIN + c0 + tx] = t[tx][ty + r];
}

// ---------------------------------------------------------------------------
// K0b: W -> fp16 swizzled blocked-atom layout
// ---------------------------------------------------------------------------
__global__ void k_wprep(const float* __restrict__ Wc) {
    int idx = blockIdx.x * 256 + threadIdx.x;
    if (idx >= COUT * 576) return;
    int co = idx / 576;
    int r  = idx - co * 576;     // k = c*9 + n
    int c  = r / 9;
    int n  = r - c * 9;
    uint32_t inner = (uint32_t)((co & 7) * 128 + c * 2);
    inner ^= (inner >> 3) & 0x70;
    *(__half*)(g_wf16 + n * 8192 + (co >> 3) * 1024 + inner) = __float2half_rn(Wc[idx]);
}

// ---------------------------------------------------------------------------
// K1: offset conv (proven R2 version)
// ---------------------------------------------------------------------------
__global__ void k_offsets(const float* __restrict__ x,
                          const float* __restrict__ Woff,
                          const float* __restrict__ boff) {
    extern __shared__ float sm1[];
    float* xs = sm1;              // [c][li][lj] : 64*18*18
    float* ws = sm1 + 64 * 324;   // [k][o pad24]

    int b  = blockIdx.z;
    int i0 = blockIdx.y * 16;
    int j0 = blockIdx.x * 16;
    int tid = threadIdx.x;

    for (int e = tid; e < 64 * 324; e += 256) {
        int c = e / 324;
        int rem = e - c * 324;
        int li = rem / 18, lj = rem - li * 18;
        int gi = i0 + li - 1, gj = j0 + lj - 1;
        float v = 0.f;
        if ((unsigned)gi < 128u && (unsigned)gj < 128u)
            v = x[((b * 64 + c) * 128 + gi) * 128 + gj];
        xs[e] = v;
    }
    for (int e = tid; e < 18 * 576; e += 256) {
        int o = e / 576;
        int k = e - o * 576;
        ws[k * K1_WS_STRIDE + o] = Woff[e];
    }
    __syncthreads();

    int ty = tid >> 4, tx = tid & 15;
    unsigned long long acc[9];
#pragma unroll
    for (int q = 0; q < 9; q++) {
        float blo = __ldg(&boff[2 * q]);
        float bhi = __ldg(&boff[2 * q + 1]);
        asm("mov.b64 %0, {%1, %2};" : "=l"(acc[q]) : "f"(blo), "f"(bhi));
    }

    for (int c = 0; c < 64; c++) {
        float xv[9];
#pragma unroll
        for (int t = 0; t < 9; t++)
            xv[t] = xs[c * 324 + (ty + t / 3) * 18 + (tx + t % 3)];
#pragma unroll
        for (int t = 0; t < 9; t++) {
            unsigned long long ss;
            asm("mov.b64 %0, {%1, %1};" : "=l"(ss) : "f"(xv[t]));
            const float* wp = ws + (c * 9 + t) * K1_WS_STRIDE;
            ulonglong2 wA = *(const ulonglong2*)(wp);
            ulonglong2 wB = *(const ulonglong2*)(wp + 4);
            ulonglong2 wC = *(const ulonglong2*)(wp + 8);
            ulonglong2 wD = *(const ulonglong2*)(wp + 12);
            unsigned long long wE = *(const unsigned long long*)(wp + 16);
            asm("fma.rn.f32x2 %0, %1, %2, %0;" : "+l"(acc[0]) : "l"(ss), "l"(wA.x));
            asm("fma.rn.f32x2 %0, %1, %2, %0;" : "+l"(acc[1]) : "l"(ss), "l"(wA.y));
            asm("fma.rn.f32x2 %0, %1, %2, %0;" : "+l"(acc[2]) : "l"(ss), "l"(wB.x));
            asm("fma.rn.f32x2 %0, %1, %2, %0;" : "+l"(acc[3]) : "l"(ss), "l"(wB.y));
            asm("fma.rn.f32x2 %0, %1, %2, %0;" : "+l"(acc[4]) : "l"(ss), "l"(wC.x));
            asm("fma.rn.f32x2 %0, %1, %2, %0;" : "+l"(acc[5]) : "l"(ss), "l"(wC.y));
            asm("fma.rn.f32x2 %0, %1, %2, %0;" : "+l"(acc[6]) : "l"(ss), "l"(wD.x));
            asm("fma.rn.f32x2 %0, %1, %2, %0;" : "+l"(acc[7]) : "l"(ss), "l"(wD.y));
            asm("fma.rn.f32x2 %0, %1, %2, %0;" : "+l"(acc[8]) : "l"(ss), "l"(wE));
        }
    }
    float* op = g_off + (((b * 128) + i0 + ty) * 128 + (j0 + tx)) * 18;
#pragma unroll
    for (int n = 0; n < 9; n++) {
        float lo, hi;
        asm("mov.b64 {%0, %1}, %2;" : "=f"(lo), "=f"(hi) : "l"(acc[n]));
        op[n]     = lo;
        op[9 + n] = hi;
    }
}

// ---------------------------------------------------------------------------
// K2: one CTA per (b, row) tile. Sample -> single MMA batch -> epilogue.
// ---------------------------------------------------------------------------
__global__ void __launch_bounds__(256, 1) __cluster_dims__(1, 1, 1)
k_mma(const float* __restrict__ Wc, float* __restrict__ out) {
    extern __shared__ unsigned char sm[];
    int tid = threadIdx.x;
    int wid = tid >> 5, lid = tid & 31;
    int b = blockIdx.x >> 7;
    int i = blockIdx.x & 127;

#if defined(__CUDA_ARCH_FEAT_SM103_ALL)
    unsigned char* A   = sm;
    unsigned char* Wsm = sm + SW_OFF;
    float* tapw = (float*)(sm + TAPW_OFF);
    int*   tapi = (int*)(sm + TAPI_OFF);
    uint32_t smem_base = smem_u32(sm);
    uint32_t ctrl      = smem_base + CTRL_OFF;
    uint32_t mbar      = ctrl + 8;

    // stage W (already swizzled fp16)
    for (int e = tid; e < SW_BYTES / 16; e += 256)
        ((uint4*)Wsm)[e] = ((const uint4*)g_wf16)[e];

    // TMEM alloc: warp 0 only; NO concurrent relinquish (race-free, test_mma style)
    if (wid == 0)
        asm volatile("tcgen05.alloc.cta_group::1.sync.aligned.shared::cta.b32 [%0], 512;"
                     :: "r"(ctrl) : "memory");
    if (tid == 0)
        asm volatile("mbarrier.init.shared.b64 [%0], 1;" :: "r"(mbar) : "memory");
    __syncthreads();
    uint32_t tmem;
    asm volatile("ld.shared.b32 %0, [%1];" : "=r"(tmem) : "r"(ctrl));

    const float* xb = g_x_nhwc + b * (128 * 128 * 64);
    for (int n = 0; n < 9; n++) {
        if (tid >= 128) {          // taps: warps 4-7, one px each
            int px = tid - 128;
            const float* ofp = g_off + (((b * 128) + i) * 128 + px) * 18;
            float pr = (float)(i + n / 3) + ofp[n];
            float pc = (float)(px + n % 3) + ofp[9 + n];
            compute_taps(pr, pc, tapi + px * 4, tapw + px * 4);
        }
        __syncthreads();

        // sampling: 2048 tasks (128 px x 16 cig), fp16 pack + STS.64
#pragma unroll
        for (int it = 0; it < 8; it++) {
            int tt  = it * 256 + tid;
            int px  = tt >> 4;
            int cig = tt & 15;
            const float* tw4 = tapw + px * 4;
            const int*   ti4 = tapi + px * 4;
            float ax = 0.f, ay = 0.f, az = 0.f, aw = 0.f;
#pragma unroll
            for (int t = 0; t < 4; t++) {
                float w = tw4[t];
                const float4 v = *(const float4*)(xb + ti4[t] + cig * 4);
                ax += w * v.x; ay += w * v.y; az += w * v.z; aw += w * v.w;
            }
            uint32_t p0, p1;
            asm("cvt.rn.f16x2.f32 %0, %1, %2;" : "=r"(p0) : "f"(ay), "f"(ax));
            asm("cvt.rn.f16x2.f32 %0, %1, %2;" : "=r"(p1) : "f"(aw), "f"(az));
            uint32_t inner = (uint32_t)((px & 7) * 128 + cig * 8);
            inner ^= (inner >> 3) & 0x70;
            *(uint2*)(A + (px >> 3) * 1024 + n * 16384 + inner) = make_uint2(p0, p1);
        }
        __syncthreads();
    }

    asm volatile("fence.proxy.async.shared::cta;" ::: "memory");
    __syncthreads();

    if (wid == 0) {
        asm volatile("tcgen05.fence::after_thread_sync;" ::: "memory");
        uint64_t a_desc0 = make_desc(smem_base);
        uint64_t b_desc0 = make_desc(smem_base + SW_OFF);
        if (elect1()) {
#pragma unroll
            for (int ks = 0; ks < 36; ks++) {
                int nn = ks >> 2, q = ks & 3;
                mma_f16_ss(tmem,
                           a_desc0 + nn * 1024 + q * 2,
                           b_desc0 + nn * 512 + q * 2,
                           IDESC_F16, ks > 0);
            }
            asm volatile(
                "tcgen05.commit.cta_group::1.mbarrier::arrive::one.shared::cluster.b64 [%0];"
                :: "r"(mbar) : "memory");
        }
    }
    __syncthreads();
    mbar_wait(mbar, 0);
    asm volatile("tcgen05.fence::after_thread_sync;" ::: "memory");

    if (wid < 4) {   // epilogue: 128 lanes x 64 cols
        uint32_t d0[32], d1[32];
        ldtm32(d0, tmem);
        ldtm32(d1, tmem + 32);
        asm volatile("tcgen05.wait::ld.sync.aligned;" ::: "memory");
        asm volatile("tcgen05.fence::before_thread_sync;" ::: "memory");
        int px = wid * 32 + lid;
        float* op = out + ((b * 64) * 128 + i) * 128 + px;
#pragma unroll
        for (int c = 0; c < 32; c++)
            op[c * 16384] = __uint_as_float(d0[c]);
#pragma unroll
        for (int c = 0; c < 32; c++)
            op[(c + 32) * 16384] = __uint_as_float(d1[c]);
    }

    __syncthreads();
    if (wid == 0)
        asm volatile("tcgen05.dealloc.cta_group::1.sync.aligned.b32 %0, 512;" :: "r"(tmem));
#else
    // ------- fallback (base arch): R2-proven f32x2 GEMM, 4 x 32px sub-tiles -
    float* smf  = (float*)sm;
    float* Ws   = smf;                  // [576][64]
    float* S    = Ws + 576 * 64;        // [32][577]
    float* tw   = S + 32 * 577;         // [288][4]
    int*   tixs = (int*)(tw + 288 * 4); // [288][4]
    float* Os   = tw;                   // [64][33] aliases taps

    for (int e = tid; e < COUT * 576; e += 256) {
        int co = e / 576;
        int k  = e - co * 576;
        Ws[k * 64 + co] = Wc[e];
    }

    for (int sub = 0; sub < 4; sub++) {
        int j0 = sub * 32;
        __syncthreads();

        for (int pn = tid; pn < 288; pn += 256) {
            int px = pn / 9;
            int nn = pn - px * 9;
            const float* ofp = g_off + (((b * 128) + i) * 128 + (j0 + px)) * 18;
            float pr = (float)(i + nn / 3) + ofp[nn];
            float pc = (float)(j0 + px + nn % 3) + ofp[9 + nn];
            compute_taps(pr, pc, tixs + pn * 4, tw + pn * 4);
        }
        __syncthreads();

        const float* xb = g_x_nhwc + b * (128 * 128 * 64);
#pragma unroll 6
        for (int it = 0; it < 18; it++) {
            int tt  = it * 256 + tid;
            int pn  = tt >> 4;
            int cig = tt & 15;
            int px  = pn / 9;
            int nn  = pn - px * 9;
            float ax = 0.f, ay = 0.f, az = 0.f, aw = 0.f;
#pragma unroll
            for (int t = 0; t < 4; t++) {
                float w = tw[pn * 4 + t];
                const float4 v = *(const float4*)(xb + tixs[pn * 4 + t] + cig * 4);
                ax += w * v.x; ay += w * v.y; az += w * v.z; aw += w * v.w;
            }
            float* sp = S + px * 577 + (cig * 4) * 9 + nn;
            sp[0] = ax; sp[9] = ay; sp[18] = az; sp[27] = aw;
        }
        __syncthreads();

        {
            int px = tid & 31;
            int cg = tid >> 5;
            const float* Srow  = S + px * 577;
            const float* Wbase = Ws + cg * 8;
            unsigned long long a01 = 0ull, a23 = 0ull, a45 = 0ull, a67 = 0ull;
#pragma unroll 8
            for (int k = 0; k < 576; k++) {
                float s = Srow[k];
                unsigned long long ss;
                asm("mov.b64 %0, {%1, %1};" : "=l"(ss) : "f"(s));
                const float* wp = Wbase + k * 64;
                ulonglong2 w0 = *(const ulonglong2*)(wp);
                ulonglong2 w1 = *(const ulonglong2*)(wp + 4);
                asm("fma.rn.f32x2 %0, %1, %2, %0;" : "+l"(a01) : "l"(ss), "l"(w0.x));
                asm("fma.rn.f32x2 %0, %1, %2, %0;" : "+l"(a23) : "l"(ss), "l"(w0.y));
                asm("fma.rn.f32x2 %0, %1, %2, %0;" : "+l"(a45) : "l"(ss), "l"(w1.x));
                asm("fma.rn.f32x2 %0, %1, %2, %0;" : "+l"(a67) : "l"(ss), "l"(w1.y));
            }
            float o[8];
            asm("mov.b64 {%0, %1}, %2;" : "=f"(o[0]), "=f"(o[1]) : "l"(a01));
            asm("mov.b64 {%0, %1}, %2;" : "=f"(o[2]), "=f"(o[3]) : "l"(a23));
            asm("mov.b64 {%0, %1}, %2;" : "=f"(o[4]), "=f"(o[5]) : "l"(a45));
            asm("mov.b64 {%0, %1}, %2;" : "=f"(o[6]), "=f"(o[7]) : "l"(a67));
            __syncthreads();
#pragma unroll
            for (int u = 0; u < 8; u++)
                Os[(cg * 8 + u) * 33 + px] = o[u];
        }
        __syncthreads();

#pragma unroll
        for (int u = 0; u < 8; u++) {
            int idx = u * 256 + tid;
            int co  = idx >> 5;
            int px  = idx & 31;
            out[((b * 64 + co) * 128 + i) * 128 + j0 + px] = Os[co * 33 + px];
        }
    }
#endif
}

// ---------------------------------------------------------------------------
extern "C" void kernel_launch(void* const* d_in, const int* in_sizes, int n_in,
                              void* d_out, int out_size) {
    const float* x    = (const float*)d_in[0];
    const float* Woff = (const float*)d_in[1];
    const float* boff = (const float*)d_in[2];
    const float* Wc   = (const float*)d_in[3];
    float* out = (float*)d_out;

    cudaFuncSetAttribute(k_offsets, cudaFuncAttributeMaxDynamicSharedMemorySize, K1_SMEM_BYTES);
    cudaFuncSetAttribute(k_mma,     cudaFuncAttributeMaxDynamicSharedMemorySize, SMEM_BYTES);

    dim3 tb0(32, 8);
    dim3 tg0(WW / 32, CIN / 32, BATCH * HH);
    k_transpose<<<tg0, tb0>>>(x);

    k_wprep<<<144, 256>>>(Wc);

    dim3 tg1(WW / 16, HH / 16, BATCH);
    k_offsets<<<tg1, 256, K1_SMEM_BYTES>>>(x, Woff, boff);

    k_mma<<<512, 256, SMEM_BYTES>>>(Wc, out);
}